// round 5
// baseline (speedup 1.0000x reference)
#include <cuda_runtime.h>
#include <math.h>

#define B_DIM 4
#define T_DIM 2048
#define C_DIM 1024
#define H_DIM 16
#define D_DIM 64
#define M_ROWS (B_DIM * T_DIM)   // 8192
#define ATTN_SCALE 0.125f

// ---------------------------------------------------------------------------
// Scratch
// ---------------------------------------------------------------------------
__device__ float g_q[M_ROWS * C_DIM];
__device__ float g_k[M_ROWS * C_DIM];
__device__ float g_v[M_ROWS * C_DIM];
__device__ float g_att[M_ROWS * C_DIM];

// ---------------------------------------------------------------------------
// tf32 helpers
// ---------------------------------------------------------------------------
__device__ __forceinline__ unsigned f2tf32(float f) {
    unsigned u;
    asm("cvt.rna.tf32.f32 %0, %1;" : "=r"(u) : "f"(f));
    return u;
}

__device__ __forceinline__ uint4 cvt4(float4 v) {
    uint4 u;
    u.x = f2tf32(v.x); u.y = f2tf32(v.y);
    u.z = f2tf32(v.z); u.w = f2tf32(v.w);
    return u;
}

// D += A(16x8,row) * B(8x8,col)  tf32 -> f32
__device__ __forceinline__ void mma_tf32(float* c, const unsigned* a, const unsigned* b) {
    asm volatile(
        "mma.sync.aligned.m16n8k8.row.col.f32.tf32.tf32.f32 "
        "{%0,%1,%2,%3}, {%4,%5,%6,%7}, {%8,%9}, {%0,%1,%2,%3};"
        : "+f"(c[0]), "+f"(c[1]), "+f"(c[2]), "+f"(c[3])
        : "r"(a[0]), "r"(a[1]), "r"(a[2]), "r"(a[3]), "r"(b[0]), "r"(b[1]));
}

// ldmatrix x4: four 8x16B matrices; per-lane row address.
__device__ __forceinline__ void ldsm4(unsigned& r0, unsigned& r1,
                                      unsigned& r2, unsigned& r3,
                                      const unsigned* p) {
    unsigned addr = (unsigned)__cvta_generic_to_shared(p);
    asm volatile("ldmatrix.sync.aligned.m8n8.x4.shared.b16 {%0,%1,%2,%3}, [%4];"
                 : "=r"(r0), "=r"(r1), "=r"(r2), "=r"(r3) : "r"(addr));
}

// ---------------------------------------------------------------------------
// GEMM: C[m][n] = sum_k A[m][k] * W[n][k] + bias[n]   (tf32 tensor-core)
// CTA tile 128x128, BK=16, 8 warps (2x4), warp tile 64x32.
// Double-buffered smem (stride 20), register prefetch, ldmatrix fragments.
// ---------------------------------------------------------------------------
__device__ __forceinline__ void gemm_body_tc(
    const float* __restrict__ A, const float* __restrict__ W,
    const float* __restrict__ bias, float* __restrict__ Cout)
{
    const int K = C_DIM;
    const int N = C_DIM;
    __shared__ unsigned As[2][128][20];
    __shared__ unsigned Ws[2][128][20];

    const int tid  = threadIdx.x;
    const int lane = tid & 31;
    const int w    = tid >> 5;
    const int g    = lane >> 2;
    const int t    = lane & 3;
    const int wm   = (w >> 2) * 64;
    const int wn   = (w & 3) * 32;
    const int m0   = blockIdx.y * 128;
    const int n0   = blockIdx.x * 128;

    // ldmatrix lane coords
    const int aRow  = wm + (lane & 15);        // + mt*16
    const int aCSel = (lane >> 4) * 4;         // 0 or 4 (+kk)
    const int bRow  = wn + (lane & 7);         // + nt*8
    const int bNtH  = (lane >> 4);             // nt within pair
    const int bCSel = ((lane >> 3) & 1) * 4;   // 0 or 4 (+kk)

    // staging coords
    const int r0 = tid >> 2;
    const int r1 = (tid + 256) >> 2;
    const int kq = (tid & 3) << 2;

    const float* Ap0 = A + (size_t)(m0 + r0) * K + kq;
    const float* Ap1 = A + (size_t)(m0 + r1) * K + kq;
    const float* Wp0 = W + (size_t)(n0 + r0) * K + kq;
    const float* Wp1 = W + (size_t)(n0 + r1) * K + kq;

    float acc[4][4][4];
#pragma unroll
    for (int mt = 0; mt < 4; mt++)
#pragma unroll
        for (int nt = 0; nt < 4; nt++)
#pragma unroll
            for (int j = 0; j < 4; j++) acc[mt][nt][j] = 0.f;

    {
        float4 pa0 = *(const float4*)(Ap0);
        float4 pa1 = *(const float4*)(Ap1);
        float4 pw0 = *(const float4*)(Wp0);
        float4 pw1 = *(const float4*)(Wp1);
        *(uint4*)&As[0][r0][kq] = cvt4(pa0);
        *(uint4*)&As[0][r1][kq] = cvt4(pa1);
        *(uint4*)&Ws[0][r0][kq] = cvt4(pw0);
        *(uint4*)&Ws[0][r1][kq] = cvt4(pw1);
    }
    __syncthreads();

    const int nIter = K / 16;   // 64
    for (int it = 0; it < nIter; it++) {
        const int cur = it & 1;
        float4 pa0, pa1, pw0, pw1;
        if (it + 1 < nIter) {
            const int ko = (it + 1) * 16;
            pa0 = *(const float4*)(Ap0 + ko);
            pa1 = *(const float4*)(Ap1 + ko);
            pw0 = *(const float4*)(Wp0 + ko);
            pw1 = *(const float4*)(Wp1 + ko);
        }

#pragma unroll
        for (int kk = 0; kk < 16; kk += 8) {
            unsigned a[4][4], b[4][2];
#pragma unroll
            for (int mt = 0; mt < 4; mt++)
                ldsm4(a[mt][0], a[mt][1], a[mt][2], a[mt][3],
                      &As[cur][aRow + mt * 16][kk + aCSel]);
#pragma unroll
            for (int pr = 0; pr < 2; pr++)
                ldsm4(b[pr * 2][0], b[pr * 2][1], b[pr * 2 + 1][0], b[pr * 2 + 1][1],
                      &Ws[cur][bRow + (pr * 2 + bNtH) * 8][kk + bCSel]);
#pragma unroll
            for (int mt = 0; mt < 4; mt++)
#pragma unroll
                for (int nt = 0; nt < 4; nt++)
                    mma_tf32(acc[mt][nt], a[mt], b[nt]);
        }

        if (it + 1 < nIter) {
            const int nxt = (it + 1) & 1;
            *(uint4*)&As[nxt][r0][kq] = cvt4(pa0);
            *(uint4*)&As[nxt][r1][kq] = cvt4(pa1);
            *(uint4*)&Ws[nxt][r0][kq] = cvt4(pw0);
            *(uint4*)&Ws[nxt][r1][kq] = cvt4(pw1);
            __syncthreads();
        }
    }

#pragma unroll
    for (int mt = 0; mt < 4; mt++) {
        const int r_lo = m0 + wm + mt * 16 + g;
#pragma unroll
        for (int nt = 0; nt < 4; nt++) {
            const int cc = n0 + wn + nt * 8 + t * 2;
            const float b0 = bias[cc], b1 = bias[cc + 1];
            float2 o;
            o.x = acc[mt][nt][0] + b0; o.y = acc[mt][nt][1] + b1;
            *(float2*)(Cout + (size_t)r_lo * N + cc) = o;
            o.x = acc[mt][nt][2] + b0; o.y = acc[mt][nt][3] + b1;
            *(float2*)(Cout + (size_t)(r_lo + 8) * N + cc) = o;
        }
    }
}

__global__ __launch_bounds__(256, 2) void gemm_qkv_kernel(
    const float* __restrict__ q_in, const float* __restrict__ k_in,
    const float* __restrict__ v_in,
    const float* __restrict__ Wq, const float* __restrict__ Wk,
    const float* __restrict__ Wv,
    const float* __restrict__ bq, const float* __restrict__ bk,
    const float* __restrict__ bv)
{
    const float* A; const float* W; const float* bias; float* Cp;
    if (blockIdx.z == 0)      { A = q_in; W = Wq; bias = bq; Cp = g_q; }
    else if (blockIdx.z == 1) { A = k_in; W = Wk; bias = bk; Cp = g_k; }
    else                      { A = v_in; W = Wv; bias = bv; Cp = g_v; }
    gemm_body_tc(A, W, bias, Cp);
}

__global__ __launch_bounds__(256, 2) void gemm_out_kernel(
    const float* __restrict__ Wo, const float* __restrict__ bo,
    float* __restrict__ out)
{
    gemm_body_tc(g_att, Wo, bo, out);
}

// ---------------------------------------------------------------------------
// FlashAttention-2 style, tf32 tensor cores + ldmatrix fragments.
// Block = (b, h, 128 q-rows), 256 threads = 8 warps; warp owns 16 q-rows.
// V staged TRANSPOSED (Vt[dim][token], stride 68) so PV fragments ldmatrix.
// Smem (u32): QP[128][68], Ks[64][68], Vt[64][68] = 69632 B.
// ---------------------------------------------------------------------------
#define ATT_SMEM_U32 (68 * (128 + 64 + 64))

__global__ __launch_bounds__(256) void attn_kernel(
    const float* __restrict__ Qg, const float* __restrict__ Kg,
    const float* __restrict__ Vg, float* __restrict__ Og)
{
    extern __shared__ unsigned smu[];
    unsigned* QP = smu;              // [128][68]  Q tile, later P tile
    unsigned* Ks = QP + 128 * 68;    // [64][68]   K tokens x dims
    unsigned* Vt = Ks + 64 * 68;     // [64][68]   dims x tokens (transposed)

    const int tid  = threadIdx.x;
    const int lane = tid & 31;
    const int w    = tid >> 5;
    const int g    = lane >> 2;
    const int t    = lane & 3;
    const int tq0  = blockIdx.x * 128;
    const int h    = blockIdx.y;
    const int b    = blockIdx.z;

    // ldmatrix lane coords (A-pattern for Q/P, B-pattern for K/Vt)
    const int aRowL = (lane & 15);
    const int aCSel = (lane >> 4) * 4;
    const int bRowL = (lane & 7);
    const int bNtH  = (lane >> 4);
    const int bCSel = ((lane >> 3) & 1) * 4;

    const size_t baseQ  = ((size_t)b * T_DIM + tq0) * C_DIM + h * D_DIM;
    const size_t baseKV = ((size_t)b * T_DIM) * C_DIM + h * D_DIM;

    // ---- load Q tile (scaled, tf32) ----
#pragma unroll
    for (int l = 0; l < 8; l++) {
        const int f = tid + 256 * l;
        const int row = f >> 4;
        const int dq = (f & 15) << 2;
        float4 v = *(const float4*)(Qg + baseQ + (size_t)row * C_DIM + dq);
        v.x *= ATTN_SCALE; v.y *= ATTN_SCALE; v.z *= ATTN_SCALE; v.w *= ATTN_SCALE;
        *(uint4*)&QP[row * 68 + dq] = cvt4(v);
    }
    __syncthreads();

    // ---- preload Q fragments via ldmatrix: 8 k-steps x 4 regs ----
    unsigned qf[8][4];
#pragma unroll
    for (int ks = 0; ks < 8; ks++)
        ldsm4(qf[ks][0], qf[ks][1], qf[ks][2], qf[ks][3],
              &QP[(16 * w + aRowL) * 68 + ks * 8 + aCSel]);

    float mi_lo = -INFINITY, mi_hi = -INFINITY;
    float li_lo = 0.f, li_hi = 0.f;
    float oacc[8][4];
#pragma unroll
    for (int ot = 0; ot < 8; ot++)
#pragma unroll
        for (int j = 0; j < 4; j++) oacc[ot][j] = 0.f;

    // V-transpose staging coords
    const int vd  = tid & 63;        // dim
    const int vtg = tid >> 6;        // token group 0..3 (16 tokens each)

    for (int kt = 0; kt < T_DIM / 64; kt++) {
        __syncthreads();
        // ---- K tile (row-major tokens x dims) ----
#pragma unroll
        for (int l = 0; l < 4; l++) {
            const int f = tid + 256 * l;
            const int row = f >> 4;
            const int dq = (f & 15) << 2;
            const float4 kv = *(const float4*)(Kg + baseKV +
                                (size_t)(kt * 64 + row) * C_DIM + dq);
            *(uint4*)&Ks[row * 68 + dq] = cvt4(kv);
        }
        // ---- V tile transposed: Vt[dim][token] ----
#pragma unroll
        for (int j = 0; j < 4; j++) {
            const int tb = vtg * 16 + j * 4;
            const float* vp = Vg + baseKV + (size_t)(kt * 64 + tb) * C_DIM + vd;
            uint4 u;
            u.x = f2tf32(vp[0]);
            u.y = f2tf32(vp[(size_t)C_DIM]);
            u.z = f2tf32(vp[(size_t)2 * C_DIM]);
            u.w = f2tf32(vp[(size_t)3 * C_DIM]);
            *(uint4*)&Vt[vd * 68 + tb] = u;
        }
        __syncthreads();

        // ---- S = Qs . K^T : each warp 16x64 ----
        float sacc[8][4];
#pragma unroll
        for (int nt = 0; nt < 8; nt++)
#pragma unroll
            for (int j = 0; j < 4; j++) sacc[nt][j] = 0.f;

#pragma unroll
        for (int ks = 0; ks < 8; ks++) {
            unsigned bf[8][2];
#pragma unroll
            for (int pr = 0; pr < 4; pr++)
                ldsm4(bf[pr * 2][0], bf[pr * 2][1],
                      bf[pr * 2 + 1][0], bf[pr * 2 + 1][1],
                      &Ks[((pr * 2 + bNtH) * 8 + bRowL) * 68 + ks * 8 + bCSel]);
#pragma unroll
            for (int nt = 0; nt < 8; nt++)
                mma_tf32(sacc[nt], qf[ks], bf[nt]);
        }

        // ---- online softmax in registers ----
        float mx_lo = -INFINITY, mx_hi = -INFINITY;
#pragma unroll
        for (int nt = 0; nt < 8; nt++) {
            mx_lo = fmaxf(mx_lo, fmaxf(sacc[nt][0], sacc[nt][1]));
            mx_hi = fmaxf(mx_hi, fmaxf(sacc[nt][2], sacc[nt][3]));
        }
        mx_lo = fmaxf(mx_lo, __shfl_xor_sync(0xffffffffu, mx_lo, 1));
        mx_lo = fmaxf(mx_lo, __shfl_xor_sync(0xffffffffu, mx_lo, 2));
        mx_hi = fmaxf(mx_hi, __shfl_xor_sync(0xffffffffu, mx_hi, 1));
        mx_hi = fmaxf(mx_hi, __shfl_xor_sync(0xffffffffu, mx_hi, 2));

        const float mnew_lo = fmaxf(mi_lo, mx_lo);
        const float mnew_hi = fmaxf(mi_hi, mx_hi);
        const float corr_lo = __expf(mi_lo - mnew_lo);
        const float corr_hi = __expf(mi_hi - mnew_hi);
        mi_lo = mnew_lo; mi_hi = mnew_hi;

        float sum_lo = 0.f, sum_hi = 0.f;
#pragma unroll
        for (int nt = 0; nt < 8; nt++) {
            sacc[nt][0] = __expf(sacc[nt][0] - mi_lo);
            sacc[nt][1] = __expf(sacc[nt][1] - mi_lo);
            sacc[nt][2] = __expf(sacc[nt][2] - mi_hi);
            sacc[nt][3] = __expf(sacc[nt][3] - mi_hi);
            sum_lo += sacc[nt][0] + sacc[nt][1];
            sum_hi += sacc[nt][2] + sacc[nt][3];
        }
        sum_lo += __shfl_xor_sync(0xffffffffu, sum_lo, 1);
        sum_lo += __shfl_xor_sync(0xffffffffu, sum_lo, 2);
        sum_hi += __shfl_xor_sync(0xffffffffu, sum_hi, 1);
        sum_hi += __shfl_xor_sync(0xffffffffu, sum_hi, 2);
        li_lo = li_lo * corr_lo + sum_lo;
        li_hi = li_hi * corr_hi + sum_hi;

#pragma unroll
        for (int ot = 0; ot < 8; ot++) {
            oacc[ot][0] *= corr_lo; oacc[ot][1] *= corr_lo;
            oacc[ot][2] *= corr_hi; oacc[ot][3] *= corr_hi;
        }

        // ---- P -> smem (warp-private rows, STS.64), then PV mma ----
        {
            const int rbase = (16 * w + g) * 68;
#pragma unroll
            for (int nt = 0; nt < 8; nt++) {
                uint2 p0, p1;
                p0.x = f2tf32(sacc[nt][0]); p0.y = f2tf32(sacc[nt][1]);
                p1.x = f2tf32(sacc[nt][2]); p1.y = f2tf32(sacc[nt][3]);
                *(uint2*)&QP[rbase + nt * 8 + t * 2] = p0;
                *(uint2*)&QP[rbase + 8 * 68 + nt * 8 + t * 2] = p1;
            }
        }
        __syncwarp();

#pragma unroll
        for (int ks = 0; ks < 8; ks++) {
            unsigned pa[4];
            ldsm4(pa[0], pa[1], pa[2], pa[3],
                  &QP[(16 * w + aRowL) * 68 + ks * 8 + aCSel]);
            unsigned vb[8][2];
#pragma unroll
            for (int pr = 0; pr < 4; pr++)
                ldsm4(vb[pr * 2][0], vb[pr * 2][1],
                      vb[pr * 2 + 1][0], vb[pr * 2 + 1][1],
                      &Vt[((pr * 2 + bNtH) * 8 + bRowL) * 68 + ks * 8 + bCSel]);
#pragma unroll
            for (int ot = 0; ot < 8; ot++)
                mma_tf32(oacc[ot], pa, vb[ot]);
        }
    }

    // ---- epilogue ----
    const float inv_lo = 1.f / li_lo;
    const float inv_hi = 1.f / li_hi;
    const int r_lo = tq0 + 16 * w + g;
    const size_t rowb_lo = ((size_t)b * T_DIM + r_lo) * C_DIM + h * D_DIM;
    const size_t rowb_hi = rowb_lo + (size_t)8 * C_DIM;
#pragma unroll
    for (int ot = 0; ot < 8; ot++) {
        const int cc = ot * 8 + t * 2;
        float2 o;
        o.x = oacc[ot][0] * inv_lo; o.y = oacc[ot][1] * inv_lo;
        *(float2*)(Og + rowb_lo + cc) = o;
        o.x = oacc[ot][2] * inv_hi; o.y = oacc[ot][3] * inv_hi;
        *(float2*)(Og + rowb_hi + cc) = o;
    }
}

// ---------------------------------------------------------------------------
// Launch
// ---------------------------------------------------------------------------
extern "C" void kernel_launch(void* const* d_in, const int* in_sizes, int n_in,
                              void* d_out, int out_size)
{
    (void)in_sizes; (void)n_in; (void)out_size;
    const float* query = (const float*)d_in[0];
    const float* key_i = (const float*)d_in[1];
    const float* value = (const float*)d_in[2];
    const float* Wq = (const float*)d_in[3];
    const float* bq = (const float*)d_in[4];
    const float* Wk = (const float*)d_in[5];
    const float* bk = (const float*)d_in[6];
    const float* Wv = (const float*)d_in[7];
    const float* bv = (const float*)d_in[8];
    const float* Wo = (const float*)d_in[9];
    const float* bo = (const float*)d_in[10];
    float* out = (float*)d_out;

    float *gq, *gk, *gv, *gatt;
    cudaGetSymbolAddress((void**)&gq, g_q);
    cudaGetSymbolAddress((void**)&gk, g_k);
    cudaGetSymbolAddress((void**)&gv, g_v);
    cudaGetSymbolAddress((void**)&gatt, g_att);

    const int attn_smem = ATT_SMEM_U32 * (int)sizeof(unsigned);  // 69632 B
    cudaFuncSetAttribute(attn_kernel,
                         cudaFuncAttributeMaxDynamicSharedMemorySize, attn_smem);

    dim3 gqkv(C_DIM / 128, M_ROWS / 128, 3);
    gemm_qkv_kernel<<<gqkv, 256>>>(query, key_i, value, Wq, Wk, Wv, bq, bk, bv);

    dim3 gatt_grid(T_DIM / 128, H_DIM, B_DIM);
    attn_kernel<<<gatt_grid, 256, attn_smem>>>(gq, gk, gv, gatt);

    dim3 gout(C_DIM / 128, M_ROWS / 128);
    gemm_out_kernel<<<gout, 256>>>(Wo, bo, out);
}

// round 6
// speedup vs baseline: 1.0453x; 1.0453x over previous
#include <cuda_runtime.h>
#include <math.h>

#define B_DIM 4
#define T_DIM 2048
#define C_DIM 1024
#define H_DIM 16
#define D_DIM 64
#define M_ROWS (B_DIM * T_DIM)   // 8192
#define ATTN_SCALE 0.125f

// ---------------------------------------------------------------------------
// Scratch: q/k/v stored as tf32-encoded bits (q pre-scaled); att stays fp32.
// ---------------------------------------------------------------------------
__device__ unsigned g_q[M_ROWS * C_DIM];
__device__ unsigned g_k[M_ROWS * C_DIM];
__device__ unsigned g_v[M_ROWS * C_DIM];
__device__ float    g_att[M_ROWS * C_DIM];

// ---------------------------------------------------------------------------
// tf32 helpers
// ---------------------------------------------------------------------------
__device__ __forceinline__ unsigned f2tf32(float f) {
    unsigned u;
    asm("cvt.rna.tf32.f32 %0, %1;" : "=r"(u) : "f"(f));
    return u;
}

__device__ __forceinline__ uint4 cvt4(float4 v) {
    uint4 u;
    u.x = f2tf32(v.x); u.y = f2tf32(v.y);
    u.z = f2tf32(v.z); u.w = f2tf32(v.w);
    return u;
}

// D += A(16x8,row) * B(8x8,col)  tf32 -> f32
__device__ __forceinline__ void mma_tf32(float* c, const unsigned* a, const unsigned* b) {
    asm volatile(
        "mma.sync.aligned.m16n8k8.row.col.f32.tf32.tf32.f32 "
        "{%0,%1,%2,%3}, {%4,%5,%6,%7}, {%8,%9}, {%0,%1,%2,%3};"
        : "+f"(c[0]), "+f"(c[1]), "+f"(c[2]), "+f"(c[3])
        : "r"(a[0]), "r"(a[1]), "r"(a[2]), "r"(a[3]), "r"(b[0]), "r"(b[1]));
}

// ldmatrix x4 (b16): per-lane row address; 32-bit elements land as A/B tf32 frags.
__device__ __forceinline__ void ldsm4(unsigned& r0, unsigned& r1,
                                      unsigned& r2, unsigned& r3,
                                      const unsigned* p) {
    unsigned addr = (unsigned)__cvta_generic_to_shared(p);
    asm volatile("ldmatrix.sync.aligned.m8n8.x4.shared.b16 {%0,%1,%2,%3}, [%4];"
                 : "=r"(r0), "=r"(r1), "=r"(r2), "=r"(r3) : "r"(addr));
}

// ---------------------------------------------------------------------------
// GEMM: C[m][n] = sum_k A[m][k] * W[n][k] + bias[n]   (tf32 tensor-core)
// CTA tile 128x128, BK=16, 8 warps (2x4), warp tile 64x32.
// Double-buffered smem (stride 20), register prefetch, ldmatrix fragments.
// TF32OUT: epilogue emits tf32 bits of (acc+bias)*oscale (for q/k/v scratch).
// ---------------------------------------------------------------------------
template<bool TF32OUT>
__device__ __forceinline__ void gemm_body_tc(
    const float* __restrict__ A, const float* __restrict__ W,
    const float* __restrict__ bias, void* __restrict__ CoutV, float oscale)
{
    const int K = C_DIM;
    const int N = C_DIM;
    __shared__ unsigned As[2][128][20];
    __shared__ unsigned Ws[2][128][20];

    const int tid  = threadIdx.x;
    const int lane = tid & 31;
    const int w    = tid >> 5;
    const int g    = lane >> 2;
    const int t    = lane & 3;
    const int wm   = (w >> 2) * 64;
    const int wn   = (w & 3) * 32;
    const int m0   = blockIdx.y * 128;
    const int n0   = blockIdx.x * 128;

    // ldmatrix lane coords
    const int aRow  = wm + (lane & 15);
    const int aCSel = (lane >> 4) * 4;
    const int bRow  = wn + (lane & 7);
    const int bNtH  = (lane >> 4);
    const int bCSel = ((lane >> 3) & 1) * 4;

    // staging coords
    const int r0 = tid >> 2;
    const int r1 = (tid + 256) >> 2;
    const int kq = (tid & 3) << 2;

    const float* Ap0 = A + (size_t)(m0 + r0) * K + kq;
    const float* Ap1 = A + (size_t)(m0 + r1) * K + kq;
    const float* Wp0 = W + (size_t)(n0 + r0) * K + kq;
    const float* Wp1 = W + (size_t)(n0 + r1) * K + kq;

    float acc[4][4][4];
#pragma unroll
    for (int mt = 0; mt < 4; mt++)
#pragma unroll
        for (int nt = 0; nt < 4; nt++)
#pragma unroll
            for (int j = 0; j < 4; j++) acc[mt][nt][j] = 0.f;

    {
        float4 pa0 = *(const float4*)(Ap0);
        float4 pa1 = *(const float4*)(Ap1);
        float4 pw0 = *(const float4*)(Wp0);
        float4 pw1 = *(const float4*)(Wp1);
        *(uint4*)&As[0][r0][kq] = cvt4(pa0);
        *(uint4*)&As[0][r1][kq] = cvt4(pa1);
        *(uint4*)&Ws[0][r0][kq] = cvt4(pw0);
        *(uint4*)&Ws[0][r1][kq] = cvt4(pw1);
    }
    __syncthreads();

    const int nIter = K / 16;   // 64
    for (int it = 0; it < nIter; it++) {
        const int cur = it & 1;
        float4 pa0, pa1, pw0, pw1;
        if (it + 1 < nIter) {
            const int ko = (it + 1) * 16;
            pa0 = *(const float4*)(Ap0 + ko);
            pa1 = *(const float4*)(Ap1 + ko);
            pw0 = *(const float4*)(Wp0 + ko);
            pw1 = *(const float4*)(Wp1 + ko);
        }

#pragma unroll
        for (int kk = 0; kk < 16; kk += 8) {
            unsigned a[4][4], b[4][2];
#pragma unroll
            for (int mt = 0; mt < 4; mt++)
                ldsm4(a[mt][0], a[mt][1], a[mt][2], a[mt][3],
                      &As[cur][aRow + mt * 16][kk + aCSel]);
#pragma unroll
            for (int pr = 0; pr < 2; pr++)
                ldsm4(b[pr * 2][0], b[pr * 2][1], b[pr * 2 + 1][0], b[pr * 2 + 1][1],
                      &Ws[cur][bRow + (pr * 2 + bNtH) * 8][kk + bCSel]);
#pragma unroll
            for (int mt = 0; mt < 4; mt++)
#pragma unroll
                for (int nt = 0; nt < 4; nt++)
                    mma_tf32(acc[mt][nt], a[mt], b[nt]);
        }

        if (it + 1 < nIter) {
            const int nxt = (it + 1) & 1;
            *(uint4*)&As[nxt][r0][kq] = cvt4(pa0);
            *(uint4*)&As[nxt][r1][kq] = cvt4(pa1);
            *(uint4*)&Ws[nxt][r0][kq] = cvt4(pw0);
            *(uint4*)&Ws[nxt][r1][kq] = cvt4(pw1);
            __syncthreads();
        }
    }

#pragma unroll
    for (int mt = 0; mt < 4; mt++) {
        const int r_lo = m0 + wm + mt * 16 + g;
#pragma unroll
        for (int nt = 0; nt < 4; nt++) {
            const int cc = n0 + wn + nt * 8 + t * 2;
            const float b0 = bias[cc], b1 = bias[cc + 1];
            if (TF32OUT) {
                unsigned* Co = (unsigned*)CoutV;
                uint2 u;
                u.x = f2tf32((acc[mt][nt][0] + b0) * oscale);
                u.y = f2tf32((acc[mt][nt][1] + b1) * oscale);
                *(uint2*)(Co + (size_t)r_lo * N + cc) = u;
                u.x = f2tf32((acc[mt][nt][2] + b0) * oscale);
                u.y = f2tf32((acc[mt][nt][3] + b1) * oscale);
                *(uint2*)(Co + (size_t)(r_lo + 8) * N + cc) = u;
            } else {
                float* Co = (float*)CoutV;
                float2 o;
                o.x = acc[mt][nt][0] + b0; o.y = acc[mt][nt][1] + b1;
                *(float2*)(Co + (size_t)r_lo * N + cc) = o;
                o.x = acc[mt][nt][2] + b0; o.y = acc[mt][nt][3] + b1;
                *(float2*)(Co + (size_t)(r_lo + 8) * N + cc) = o;
            }
        }
    }
}

__global__ __launch_bounds__(256, 2) void gemm_qkv_kernel(
    const float* __restrict__ q_in, const float* __restrict__ k_in,
    const float* __restrict__ v_in,
    const float* __restrict__ Wq, const float* __restrict__ Wk,
    const float* __restrict__ Wv,
    const float* __restrict__ bq, const float* __restrict__ bk,
    const float* __restrict__ bv)
{
    const float* A; const float* W; const float* bias; unsigned* Cp; float sc;
    if (blockIdx.z == 0)      { A = q_in; W = Wq; bias = bq; Cp = g_q; sc = ATTN_SCALE; }
    else if (blockIdx.z == 1) { A = k_in; W = Wk; bias = bk; Cp = g_k; sc = 1.f; }
    else                      { A = v_in; W = Wv; bias = bv; Cp = g_v; sc = 1.f; }
    gemm_body_tc<true>(A, W, bias, Cp, sc);
}

__global__ __launch_bounds__(256, 2) void gemm_out_kernel(
    const float* __restrict__ Wo, const float* __restrict__ bo,
    float* __restrict__ out)
{
    gemm_body_tc<false>(g_att, Wo, bo, out, 1.f);
}

// ---------------------------------------------------------------------------
// FlashAttention-2, tf32 tensor cores. Inputs pre-converted to tf32 bits.
// Block = (b, h, 128 q-rows), 256 threads = 8 warps; warp owns 16 q-rows.
// K/V tiles double-buffered (64 tokens); pure uint4 staging (no cvt).
// ldmatrix for Q/K/P fragments; V row-major with scalar LDS fragments.
// Smem (u32): QP[128][68], Ks[2][64][68], Vs[2][64][72] = 106496 B.
// ---------------------------------------------------------------------------
#define ATT_SMEM_U32 (128 * 68 + 2 * 64 * 68 + 2 * 64 * 72)

__global__ __launch_bounds__(256, 2) void attn_kernel(
    const unsigned* __restrict__ Qg, const unsigned* __restrict__ Kg,
    const unsigned* __restrict__ Vg, float* __restrict__ Og)
{
    extern __shared__ unsigned smu[];
    unsigned* QP = smu;                    // [128][68]  Q tile, later P tile
    unsigned* Ks = QP + 128 * 68;          // [2][64][68]
    unsigned* Vs = Ks + 2 * 64 * 68;       // [2][64][72]

    const int tid  = threadIdx.x;
    const int lane = tid & 31;
    const int w    = tid >> 5;
    const int g    = lane >> 2;
    const int t    = lane & 3;
    const int tq0  = blockIdx.x * 128;
    const int h    = blockIdx.y;
    const int b    = blockIdx.z;

    // ldmatrix lane coords
    const int aRowL = (lane & 15);
    const int aCSel = (lane >> 4) * 4;
    const int bRowL = (lane & 7);
    const int bNtH  = (lane >> 4);
    const int bCSel = ((lane >> 3) & 1) * 4;

    const size_t baseQ  = ((size_t)b * T_DIM + tq0) * C_DIM + h * D_DIM;
    const size_t baseKV = ((size_t)b * T_DIM) * C_DIM + h * D_DIM;

    // staging coords (shared by Q/K/V loops)
    const int sRow = tid >> 4;             // + 64*l/16... see loops
    const int sCol = (tid & 15) << 2;

    // ---- load Q tile (already scaled tf32 bits) ----
#pragma unroll
    for (int l = 0; l < 8; l++) {
        const int row = (tid + 256 * l) >> 4;
        *(uint4*)&QP[row * 68 + sCol] =
            *(const uint4*)(Qg + baseQ + (size_t)row * C_DIM + sCol);
    }
    __syncthreads();

    // ---- preload Q fragments via ldmatrix ----
    unsigned qf[8][4];
#pragma unroll
    for (int ks = 0; ks < 8; ks++)
        ldsm4(qf[ks][0], qf[ks][1], qf[ks][2], qf[ks][3],
              &QP[(16 * w + aRowL) * 68 + ks * 8 + aCSel]);

    float mi_lo = -INFINITY, mi_hi = -INFINITY;
    float li_lo = 0.f, li_hi = 0.f;
    float oacc[8][4];
#pragma unroll
    for (int ot = 0; ot < 8; ot++)
#pragma unroll
        for (int j = 0; j < 4; j++) oacc[ot][j] = 0.f;

    // ---- prologue: stage KV tile 0 into buffer 0 ----
#pragma unroll
    for (int l = 0; l < 4; l++) {
        const int row = (tid + 256 * l) >> 4;
        const size_t gi = baseKV + (size_t)row * C_DIM + sCol;
        *(uint4*)&Ks[row * 68 + sCol] = *(const uint4*)(Kg + gi);
        *(uint4*)&Vs[row * 72 + sCol] = *(const uint4*)(Vg + gi);
    }
    __syncthreads();

    const int nKT = T_DIM / 64;   // 32
    for (int kt = 0; kt < nKT; kt++) {
        const int cur = kt & 1;
        unsigned* KsC = Ks + cur * 64 * 68;
        unsigned* VsC = Vs + cur * 64 * 72;

        // prefetch next tile into registers
        uint4 pk[4], pv[4];
        if (kt + 1 < nKT) {
#pragma unroll
            for (int l = 0; l < 4; l++) {
                const int row = (tid + 256 * l) >> 4;
                const size_t gi = baseKV + (size_t)((kt + 1) * 64 + row) * C_DIM + sCol;
                pk[l] = *(const uint4*)(Kg + gi);
                pv[l] = *(const uint4*)(Vg + gi);
            }
        }

        // ---- S = Qs . K^T : each warp 16x64 ----
        float sacc[8][4];
#pragma unroll
        for (int nt = 0; nt < 8; nt++)
#pragma unroll
            for (int j = 0; j < 4; j++) sacc[nt][j] = 0.f;

#pragma unroll
        for (int ks = 0; ks < 8; ks++) {
            unsigned bf[8][2];
#pragma unroll
            for (int pr = 0; pr < 4; pr++)
                ldsm4(bf[pr * 2][0], bf[pr * 2][1],
                      bf[pr * 2 + 1][0], bf[pr * 2 + 1][1],
                      &KsC[((pr * 2 + bNtH) * 8 + bRowL) * 68 + ks * 8 + bCSel]);
#pragma unroll
            for (int nt = 0; nt < 8; nt++)
                mma_tf32(sacc[nt], qf[ks], bf[nt]);
        }

        // ---- online softmax in registers ----
        float mx_lo = -INFINITY, mx_hi = -INFINITY;
#pragma unroll
        for (int nt = 0; nt < 8; nt++) {
            mx_lo = fmaxf(mx_lo, fmaxf(sacc[nt][0], sacc[nt][1]));
            mx_hi = fmaxf(mx_hi, fmaxf(sacc[nt][2], sacc[nt][3]));
        }
        mx_lo = fmaxf(mx_lo, __shfl_xor_sync(0xffffffffu, mx_lo, 1));
        mx_lo = fmaxf(mx_lo, __shfl_xor_sync(0xffffffffu, mx_lo, 2));
        mx_hi = fmaxf(mx_hi, __shfl_xor_sync(0xffffffffu, mx_hi, 1));
        mx_hi = fmaxf(mx_hi, __shfl_xor_sync(0xffffffffu, mx_hi, 2));

        const float mnew_lo = fmaxf(mi_lo, mx_lo);
        const float mnew_hi = fmaxf(mi_hi, mx_hi);
        const float corr_lo = __expf(mi_lo - mnew_lo);
        const float corr_hi = __expf(mi_hi - mnew_hi);
        mi_lo = mnew_lo; mi_hi = mnew_hi;

        float sum_lo = 0.f, sum_hi = 0.f;
#pragma unroll
        for (int nt = 0; nt < 8; nt++) {
            sacc[nt][0] = __expf(sacc[nt][0] - mi_lo);
            sacc[nt][1] = __expf(sacc[nt][1] - mi_lo);
            sacc[nt][2] = __expf(sacc[nt][2] - mi_hi);
            sacc[nt][3] = __expf(sacc[nt][3] - mi_hi);
            sum_lo += sacc[nt][0] + sacc[nt][1];
            sum_hi += sacc[nt][2] + sacc[nt][3];
        }
        sum_lo += __shfl_xor_sync(0xffffffffu, sum_lo, 1);
        sum_lo += __shfl_xor_sync(0xffffffffu, sum_lo, 2);
        sum_hi += __shfl_xor_sync(0xffffffffu, sum_hi, 1);
        sum_hi += __shfl_xor_sync(0xffffffffu, sum_hi, 2);
        li_lo = li_lo * corr_lo + sum_lo;
        li_hi = li_hi * corr_hi + sum_hi;

#pragma unroll
        for (int ot = 0; ot < 8; ot++) {
            oacc[ot][0] *= corr_lo; oacc[ot][1] *= corr_lo;
            oacc[ot][2] *= corr_hi; oacc[ot][3] *= corr_hi;
        }

        // ---- P -> smem (warp-private rows, STS.64), then PV mma ----
        {
            const int rbase = (16 * w + g) * 68;
#pragma unroll
            for (int nt = 0; nt < 8; nt++) {
                uint2 p0, p1;
                p0.x = f2tf32(sacc[nt][0]); p0.y = f2tf32(sacc[nt][1]);
                p1.x = f2tf32(sacc[nt][2]); p1.y = f2tf32(sacc[nt][3]);
                *(uint2*)&QP[rbase + nt * 8 + t * 2] = p0;
                *(uint2*)&QP[rbase + 8 * 68 + nt * 8 + t * 2] = p1;
            }
        }
        __syncwarp();

#pragma unroll
        for (int ks = 0; ks < 8; ks++) {
            unsigned pa[4];
            ldsm4(pa[0], pa[1], pa[2], pa[3],
                  &QP[(16 * w + aRowL) * 68 + ks * 8 + aCSel]);
            unsigned vb[8][2];
#pragma unroll
            for (int ot = 0; ot < 8; ot++) {
                vb[ot][0] = VsC[(ks * 8 + t) * 72 + ot * 8 + g];
                vb[ot][1] = VsC[(ks * 8 + t + 4) * 72 + ot * 8 + g];
            }
#pragma unroll
            for (int ot = 0; ot < 8; ot++)
                mma_tf32(oacc[ot], pa, vb[ot]);
        }

        // ---- commit prefetched tile, one sync per iteration ----
        if (kt + 1 < nKT) {
            unsigned* KsN = Ks + ((kt + 1) & 1) * 64 * 68;
            unsigned* VsN = Vs + ((kt + 1) & 1) * 64 * 72;
#pragma unroll
            for (int l = 0; l < 4; l++) {
                const int row = (tid + 256 * l) >> 4;
                *(uint4*)&KsN[row * 68 + sCol] = pk[l];
                *(uint4*)&VsN[row * 72 + sCol] = pv[l];
            }
            __syncthreads();
        }
    }

    // ---- epilogue ----
    const float inv_lo = 1.f / li_lo;
    const float inv_hi = 1.f / li_hi;
    const int r_lo = tq0 + 16 * w + g;
    const size_t rowb_lo = ((size_t)b * T_DIM + r_lo) * C_DIM + h * D_DIM;
    const size_t rowb_hi = rowb_lo + (size_t)8 * C_DIM;
#pragma unroll
    for (int ot = 0; ot < 8; ot++) {
        const int cc = ot * 8 + t * 2;
        float2 o;
        o.x = oacc[ot][0] * inv_lo; o.y = oacc[ot][1] * inv_lo;
        *(float2*)(Og + rowb_lo + cc) = o;
        o.x = oacc[ot][2] * inv_hi; o.y = oacc[ot][3] * inv_hi;
        *(float2*)(Og + rowb_hi + cc) = o;
    }
}

// ---------------------------------------------------------------------------
// Launch
// ---------------------------------------------------------------------------
extern "C" void kernel_launch(void* const* d_in, const int* in_sizes, int n_in,
                              void* d_out, int out_size)
{
    (void)in_sizes; (void)n_in; (void)out_size;
    const float* query = (const float*)d_in[0];
    const float* key_i = (const float*)d_in[1];
    const float* value = (const float*)d_in[2];
    const float* Wq = (const float*)d_in[3];
    const float* bq = (const float*)d_in[4];
    const float* Wk = (const float*)d_in[5];
    const float* bk = (const float*)d_in[6];
    const float* Wv = (const float*)d_in[7];
    const float* bv = (const float*)d_in[8];
    const float* Wo = (const float*)d_in[9];
    const float* bo = (const float*)d_in[10];
    float* out = (float*)d_out;

    unsigned *gq, *gk, *gv;
    cudaGetSymbolAddress((void**)&gq, g_q);
    cudaGetSymbolAddress((void**)&gk, g_k);
    cudaGetSymbolAddress((void**)&gv, g_v);
    float* gatt;
    cudaGetSymbolAddress((void**)&gatt, g_att);

    const int attn_smem = ATT_SMEM_U32 * (int)sizeof(unsigned);  // 106496 B
    cudaFuncSetAttribute(attn_kernel,
                         cudaFuncAttributeMaxDynamicSharedMemorySize, attn_smem);

    dim3 gqkv(C_DIM / 128, M_ROWS / 128, 3);
    gemm_qkv_kernel<<<gqkv, 256>>>(query, key_i, value, Wq, Wk, Wv, bq, bk, bv);

    dim3 gatt_grid(T_DIM / 128, H_DIM, B_DIM);
    attn_kernel<<<gatt_grid, 256, attn_smem>>>(gq, gk, gv, gatt);

    dim3 gout(C_DIM / 128, M_ROWS / 128);
    gemm_out_kernel<<<gout, 256>>>(Wo, bo, out);
}